// round 3
// baseline (speedup 1.0000x reference)
#include <cuda_runtime.h>
#include <cstdint>

// TPThird: per-sample equivariant tensor product. NS=48, NV=10, Z=50000.
// x1: (Z,108) = [0e:48 | 1o:10x3 | 1e:10x3]
// x2: (Z,9)   = [0e:1 | 1o:3 | 2e:5]
// weights: (Z,4344), out: (Z,156) = [r0e:48 | r1o:30 | r1e:30 | r0o:48]
//
// Persistent blocks, 2-stage double-buffered TMA (cp.async.bulk) pipeline.

#define X1DIM 108
#define WNUM  4344
#define OUTDIM 156

#define OW00  0
#define OW01  2304
#define OW10  2784
#define OW110 2884
#define OW112 3364
#define OW12  3464
#define OW20  3564
#define OW211 3664
#define OW213 3764
#define OW22  4244

#define NBLOCKS (148 * 6)

__device__ __forceinline__ uint32_t smem_u32(const void* p) {
    return (uint32_t)__cvta_generic_to_shared(p);
}

__device__ __forceinline__ void mbar_wait(uint32_t mb, uint32_t phase) {
    uint32_t done;
    asm volatile(
        "{\n\t"
        ".reg .pred P;\n\t"
        "WAIT_%=:\n\t"
        "mbarrier.try_wait.parity.shared.b64 P, [%1], %2;\n\t"
        "selp.b32 %0, 1, 0, P;\n\t"
        "@!P bra WAIT_%=;\n\t"
        "}"
        : "=r"(done) : "r"(mb), "r"(phase) : "memory");
}

__device__ __forceinline__ void issue_tma(uint32_t mb,
                                          float* sW, float* sx1,
                                          const float* gW, const float* gx1) {
    const uint32_t total_bytes = (WNUM + X1DIM) * 4;
    asm volatile("mbarrier.arrive.expect_tx.shared.b64 _, [%0], %1;"
                 :: "r"(mb), "r"(total_bytes) : "memory");
    asm volatile("cp.async.bulk.shared::cta.global.mbarrier::complete_tx::bytes "
                 "[%0], [%1], %2, [%3];"
                 :: "r"(smem_u32(sW)), "l"(gW),
                    "r"((uint32_t)(WNUM * 4)), "r"(mb) : "memory");
    asm volatile("cp.async.bulk.shared::cta.global.mbarrier::complete_tx::bytes "
                 "[%0], [%1], %2, [%3];"
                 :: "r"(smem_u32(sx1)), "l"(gx1),
                    "r"((uint32_t)(X1DIM * 4)), "r"(mb) : "memory");
}

__global__ __launch_bounds__(192, 6)
void tpthird_kernel(const float* __restrict__ x1,
                    const float* __restrict__ x2,
                    const float* __restrict__ W,
                    float* __restrict__ out,
                    int Z)
{
    const int tid = threadIdx.x;
    const int stride = gridDim.x;

    __shared__ __align__(16) float s_W[2][WNUM];
    __shared__ __align__(16) float s_x1[2][X1DIM];
    __shared__ float s_d1o[10], s_d1e[10];
    __shared__ float s_t112[10][3], s_t211[10][3];
    __shared__ float s_t12[10][3],  s_t22[10][3];
    __shared__ __align__(8) unsigned long long s_mbar[2];

    const uint32_t mb0 = smem_u32(&s_mbar[0]);
    const uint32_t mb1 = smem_u32(&s_mbar[1]);

    if (tid < 2) {
        asm volatile("mbarrier.init.shared.b64 [%0], 1;"
                     :: "r"(tid == 0 ? mb0 : mb1) : "memory");
    }
    __syncthreads();

    const int z0 = blockIdx.x;

    // Prologue: prefetch stages 0 and 1.
    if (tid == 0) {
        if (z0 < Z)
            issue_tma(mb0, s_W[0], s_x1[0],
                      W + (size_t)z0 * WNUM, x1 + (size_t)z0 * X1DIM);
        if (z0 + stride < Z)
            issue_tma(mb1, s_W[1], s_x1[1],
                      W + (size_t)(z0 + stride) * WNUM,
                      x1 + (size_t)(z0 + stride) * X1DIM);
    }

    const float N0E  = 0.1313064328597226f;   // sqrt(1/58)
    const float N1O  = 0.1961161351381841f;   // sqrt(3/78)
    const float N1E  = 0.3162277660168379f;   // sqrt(1/10)
    const float N0O  = 0.3162277660168379f;   // sqrt(1/10)
    const float ISQ3 = 0.5773502691896258f;   // 1/sqrt(3)

    int i = 0;
    for (int z = z0; z < Z; z += stride, i++) {
        const int   st    = i & 1;
        const uint32_t mb = st ? mb1 : mb0;
        const uint32_t ph = (i >> 1) & 1;

        const float* __restrict__ x2z = x2 + (size_t)z * 9;
        // Issue x2 load early (independent of mbarrier).
        const float x20 = __ldg(&x2z[0]);

        mbar_wait(mb, ph);

        const float* __restrict__ Wb  = s_W[st];
        const float* __restrict__ x1b = s_x1[st];

        // --- per-u derived activations (10 threads) ---
        if (tid < 10) {
            const int u = tid;
            const float a0 = x1b[48 + u*3 + 0];
            const float a1 = x1b[48 + u*3 + 1];
            const float a2 = x1b[48 + u*3 + 2];
            const float e0 = x1b[78 + u*3 + 0];
            const float e1 = x1b[78 + u*3 + 1];
            const float e2 = x1b[78 + u*3 + 2];
            const float b0 = __ldg(&x2z[1]), b1 = __ldg(&x2z[2]), b2 = __ldg(&x2z[3]);
            const float c0 = __ldg(&x2z[4]), c1 = __ldg(&x2z[5]), c2 = __ldg(&x2z[6]);
            const float c3 = __ldg(&x2z[7]), c4 = __ldg(&x2z[8]);

            s_d1o[u] = a0*b0 + a1*b1 + a2*b2;
            s_d1e[u] = e0*b0 + e1*b1 + e2*b2;

            const float IS6 = 0.4082482904638630164f;  // 1/sqrt(6)
            s_t112[u][0] = (a1*b2 - a2*b1) * IS6;
            s_t112[u][1] = (a2*b0 - a0*b2) * IS6;
            s_t112[u][2] = (a0*b1 - a1*b0) * IS6;
            s_t211[u][0] = (e1*b2 - e2*b1) * IS6;
            s_t211[u][1] = (e2*b0 - e0*b2) * IS6;
            s_t211[u][2] = (e0*b1 - e1*b0) * IS6;

            const float S10 = 0.3162277660168379332f;  // 1/sqrt(10)
            const float S30 = 0.1825741858350553712f;  // 1/sqrt(30)
            s_t12[u][0] =  S10*a2*c0 - S30*a0*c2 - S10*a0*c4 + S10*a1*c1;
            s_t12[u][1] =  S10*a2*c3 + S10*a0*c1 + 2.0f*S30*a1*c2;
            s_t12[u][2] = -S30*a2*c2 + S10*a2*c4 + S10*a0*c0 + S10*a1*c3;
            s_t22[u][0] =  S10*e2*c0 - S30*e0*c2 - S10*e0*c4 + S10*e1*c1;
            s_t22[u][1] =  S10*e2*c3 + S10*e0*c1 + 2.0f*S30*e1*c2;
            s_t22[u][2] = -S30*e2*c2 + S10*e2*c4 + S10*e0*c0 + S10*e1*c3;
        }
        __syncthreads();

        float* __restrict__ oz = out + (size_t)z * OUTDIM;

        // Warp-aligned output ownership:
        //   warps 0-1 -> r0e (48) | warp 2 -> r1o (30) | warp 3 -> r1e (30) | warps 4-5 -> r0o (48)
        if (tid < 64) {
            if (tid < 48) {
                const int w = tid;
                float acc = 0.0f;
                #pragma unroll
                for (int u = 0; u < 48; u++)
                    acc += x1b[u] * Wb[OW00 + u*48 + w];
                acc *= x20;
                float acc2 = 0.0f;
                #pragma unroll
                for (int u = 0; u < 10; u++)
                    acc2 += s_d1o[u] * Wb[OW110 + u*48 + w];
                oz[w] = N0E * (acc + ISQ3 * acc2);
            }
        } else if (tid < 96) {
            const int idx = tid - 64;
            if (idx < 30) {
                const int w = idx / 3, j = idx % 3;
                const float x2j = __ldg(&x2z[1 + j]);
                float p01 = 0.0f;
                #pragma unroll
                for (int u = 0; u < 48; u++)
                    p01 += x1b[u] * Wb[OW01 + u*10 + w];
                float a10 = 0.0f, a12 = 0.0f, a211 = 0.0f;
                #pragma unroll
                for (int u = 0; u < 10; u++) {
                    a10  += x1b[48 + u*3 + j] * Wb[OW10  + u*10 + w];
                    a12  += s_t12[u][j]       * Wb[OW12  + u*10 + w];
                    a211 += s_t211[u][j]      * Wb[OW211 + u*10 + w];
                }
                oz[48 + idx] = N1O * (ISQ3 * (x2j * p01 + x20 * a10) + a12 + a211);
            }
        } else if (tid < 128) {
            const int idx = tid - 96;
            if (idx < 30) {
                const int w = idx / 3, k = idx % 3;
                float a112 = 0.0f, a20 = 0.0f, a22 = 0.0f;
                #pragma unroll
                for (int u = 0; u < 10; u++) {
                    a112 += s_t112[u][k]      * Wb[OW112 + u*10 + w];
                    a20  += x1b[78 + u*3 + k] * Wb[OW20  + u*10 + w];
                    a22  += s_t22[u][k]       * Wb[OW22  + u*10 + w];
                }
                oz[78 + idx] = N1E * (a112 + ISQ3 * x20 * a20 + a22);
            }
        } else {
            const int w = tid - 128;
            if (w < 48) {
                float acc = 0.0f;
                #pragma unroll
                for (int u = 0; u < 10; u++)
                    acc += s_d1e[u] * Wb[OW213 + u*48 + w];
                oz[108 + w] = N0O * ISQ3 * acc;
            }
        }
        __syncthreads();  // all reads of stage `st` complete -> safe to refill

        // Refill this stage for sample z + 2*stride.
        const int zn = z + 2 * stride;
        if (tid == 0 && zn < Z) {
            issue_tma(mb, s_W[st], s_x1[st],
                      W + (size_t)zn * WNUM, x1 + (size_t)zn * X1DIM);
        }
    }
}

extern "C" void kernel_launch(void* const* d_in, const int* in_sizes, int n_in,
                              void* d_out, int out_size)
{
    const float* x1 = (const float*)d_in[0];
    const float* x2 = (const float*)d_in[1];
    const float* W  = (const float*)d_in[2];
    float* out = (float*)d_out;

    const int Z = in_sizes[0] / X1DIM;
    int grid = NBLOCKS < Z ? NBLOCKS : Z;
    tpthird_kernel<<<grid, 192>>>(x1, x2, W, out, Z);
}

// round 4
// speedup vs baseline: 1.2596x; 1.2596x over previous
#include <cuda_runtime.h>
#include <cstdint>

// TPThird: per-sample equivariant tensor product. NS=48, NV=10, Z=50000.
// x1: (Z,108) = [0e:48 | 1o:10x3 | 1e:10x3]
// x2: (Z,9)   = [0e:1 | 1o:3 | 2e:5]
// weights: (Z,4344), out: (Z,156) = [r0e:48 | r1o:30 | r1e:30 | r0o:48]
//
// One block per sample; TMA bulk-copies the weight row + x1 to SMEM.
// No block-wide barrier after the mbarrier wait: all derived activations
// are computed warp-locally (lanes 0-9, __syncwarp only).

#define X1DIM 108
#define WNUM  4344
#define OUTDIM 156

#define OW00  0
#define OW01  2304
#define OW10  2784
#define OW110 2884
#define OW112 3364
#define OW12  3464
#define OW20  3564
#define OW211 3664
#define OW213 3764
#define OW22  4244

__device__ __forceinline__ uint32_t smem_u32(const void* p) {
    return (uint32_t)__cvta_generic_to_shared(p);
}

__device__ __forceinline__ void mbar_wait(uint32_t mb, uint32_t phase) {
    uint32_t done;
    asm volatile(
        "{\n\t"
        ".reg .pred P;\n\t"
        "WAIT_%=:\n\t"
        "mbarrier.try_wait.parity.shared.b64 P, [%1], %2;\n\t"
        "selp.b32 %0, 1, 0, P;\n\t"
        "@!P bra WAIT_%=;\n\t"
        "}"
        : "=r"(done) : "r"(mb), "r"(phase) : "memory");
}

__global__ __launch_bounds__(192, 10)
void tpthird_kernel(const float* __restrict__ x1,
                    const float* __restrict__ x2,
                    const float* __restrict__ W,
                    float* __restrict__ out)
{
    const int z   = blockIdx.x;
    const int tid = threadIdx.x;
    const int wid = tid >> 5;
    const int lid = tid & 31;

    __shared__ __align__(16) float s_W[WNUM];
    __shared__ __align__(16) float s_x1[X1DIM];
    __shared__ float s_d1o[2][10];          // warp-local copies (warps 0,1)
    __shared__ float s_d1e[2][10];          // warps 4,5
    __shared__ float s_t12[10][3], s_t211[10][3];   // warp 2
    __shared__ float s_t112[10][3], s_t22[10][3];   // warp 3
    __shared__ __align__(8) unsigned long long s_mbar;

    const uint32_t mb = smem_u32(&s_mbar);

    // tid 0: init barrier, fence to async proxy, issue TMA immediately.
    if (tid == 0) {
        asm volatile("mbarrier.init.shared.b64 [%0], 1;" :: "r"(mb) : "memory");
        asm volatile("fence.proxy.async.shared::cta;" ::: "memory");
        const uint32_t total_bytes = (WNUM + X1DIM) * 4;
        asm volatile("mbarrier.arrive.expect_tx.shared.b64 _, [%0], %1;"
                     :: "r"(mb), "r"(total_bytes) : "memory");
        asm volatile("cp.async.bulk.shared::cta.global.mbarrier::complete_tx::bytes "
                     "[%0], [%1], %2, [%3];"
                     :: "r"(smem_u32(s_W)), "l"(W + (size_t)z * WNUM),
                        "r"((uint32_t)(WNUM * 4)), "r"(mb) : "memory");
        asm volatile("cp.async.bulk.shared::cta.global.mbarrier::complete_tx::bytes "
                     "[%0], [%1], %2, [%3];"
                     :: "r"(smem_u32(s_x1)), "l"(x1 + (size_t)z * X1DIM),
                        "r"((uint32_t)(X1DIM * 4)), "r"(mb) : "memory");
    }
    __syncthreads();   // other threads: barrier is initialized before try_wait

    const float* __restrict__ x2z = x2 + (size_t)z * 9;
    const float x20 = __ldg(&x2z[0]);   // overlaps with mbar wait

    mbar_wait(mb, 0);

    const float N0E  = 0.1313064328597226f;   // sqrt(1/58)
    const float N1O  = 0.1961161351381841f;   // sqrt(3/78)
    const float N1E  = 0.3162277660168379f;   // sqrt(1/10)
    const float N0O  = 0.3162277660168379f;   // sqrt(1/10)
    const float ISQ3 = 0.5773502691896258f;   // 1/sqrt(3)
    const float IS6  = 0.4082482904638630164f; // 1/sqrt(6)
    const float S10  = 0.3162277660168379332f; // 1/sqrt(10)
    const float S30  = 0.1825741858350553712f; // 1/sqrt(30)

    float* __restrict__ oz = out + (size_t)z * OUTDIM;

    // ---- per-warp local precompute (lanes 0-9), then __syncwarp only ----
    if (wid < 2) {
        // warps 0,1 -> r0e (48 outputs over 64 lanes); need d1o[u]
        if (lid < 10) {
            const int u = lid;
            const float b0 = __ldg(&x2z[1]), b1 = __ldg(&x2z[2]), b2 = __ldg(&x2z[3]);
            s_d1o[wid][u] = s_x1[48 + u*3 + 0]*b0 + s_x1[48 + u*3 + 1]*b1
                          + s_x1[48 + u*3 + 2]*b2;
        }
        __syncwarp();
        const int w = tid;
        if (w < 48) {
            float acc = 0.0f;
            #pragma unroll
            for (int u = 0; u < 48; u++)
                acc += s_x1[u] * s_W[OW00 + u*48 + w];
            acc *= x20;
            float acc2 = 0.0f;
            #pragma unroll
            for (int u = 0; u < 10; u++)
                acc2 += s_d1o[wid][u] * s_W[OW110 + u*48 + w];
            oz[w] = N0E * (acc + ISQ3 * acc2);
        }
    } else if (wid == 2) {
        // warp 2 -> r1o (30 outputs); needs t12, t211
        if (lid < 10) {
            const int u = lid;
            const float a0 = s_x1[48 + u*3 + 0];
            const float a1 = s_x1[48 + u*3 + 1];
            const float a2 = s_x1[48 + u*3 + 2];
            const float e0 = s_x1[78 + u*3 + 0];
            const float e1 = s_x1[78 + u*3 + 1];
            const float e2 = s_x1[78 + u*3 + 2];
            const float b0 = __ldg(&x2z[1]), b1 = __ldg(&x2z[2]), b2 = __ldg(&x2z[3]);
            const float c0 = __ldg(&x2z[4]), c1 = __ldg(&x2z[5]), c2 = __ldg(&x2z[6]);
            const float c3 = __ldg(&x2z[7]), c4 = __ldg(&x2z[8]);
            s_t211[u][0] = (e1*b2 - e2*b1) * IS6;
            s_t211[u][1] = (e2*b0 - e0*b2) * IS6;
            s_t211[u][2] = (e0*b1 - e1*b0) * IS6;
            s_t12[u][0] =  S10*a2*c0 - S30*a0*c2 - S10*a0*c4 + S10*a1*c1;
            s_t12[u][1] =  S10*a2*c3 + S10*a0*c1 + 2.0f*S30*a1*c2;
            s_t12[u][2] = -S30*a2*c2 + S10*a2*c4 + S10*a0*c0 + S10*a1*c3;
        }
        __syncwarp();
        const int idx = lid;
        if (idx < 30) {
            const int w = idx / 3, j = idx % 3;
            const float x2j = __ldg(&x2z[1 + j]);
            float p01 = 0.0f;
            #pragma unroll
            for (int u = 0; u < 48; u++)
                p01 += s_x1[u] * s_W[OW01 + u*10 + w];
            float a10 = 0.0f, a12 = 0.0f, a211 = 0.0f;
            #pragma unroll
            for (int u = 0; u < 10; u++) {
                a10  += s_x1[48 + u*3 + j] * s_W[OW10  + u*10 + w];
                a12  += s_t12[u][j]        * s_W[OW12  + u*10 + w];
                a211 += s_t211[u][j]       * s_W[OW211 + u*10 + w];
            }
            oz[48 + idx] = N1O * (ISQ3 * (x2j * p01 + x20 * a10) + a12 + a211);
        }
    } else if (wid == 3) {
        // warp 3 -> r1e (30 outputs); needs t112, t22
        if (lid < 10) {
            const int u = lid;
            const float a0 = s_x1[48 + u*3 + 0];
            const float a1 = s_x1[48 + u*3 + 1];
            const float a2 = s_x1[48 + u*3 + 2];
            const float e0 = s_x1[78 + u*3 + 0];
            const float e1 = s_x1[78 + u*3 + 1];
            const float e2 = s_x1[78 + u*3 + 2];
            const float b0 = __ldg(&x2z[1]), b1 = __ldg(&x2z[2]), b2 = __ldg(&x2z[3]);
            const float c0 = __ldg(&x2z[4]), c1 = __ldg(&x2z[5]), c2 = __ldg(&x2z[6]);
            const float c3 = __ldg(&x2z[7]), c4 = __ldg(&x2z[8]);
            s_t112[u][0] = (a1*b2 - a2*b1) * IS6;
            s_t112[u][1] = (a2*b0 - a0*b2) * IS6;
            s_t112[u][2] = (a0*b1 - a1*b0) * IS6;
            s_t22[u][0] =  S10*e2*c0 - S30*e0*c2 - S10*e0*c4 + S10*e1*c1;
            s_t22[u][1] =  S10*e2*c3 + S10*e0*c1 + 2.0f*S30*e1*c2;
            s_t22[u][2] = -S30*e2*c2 + S10*e2*c4 + S10*e0*c0 + S10*e1*c3;
        }
        __syncwarp();
        const int idx = lid;
        if (idx < 30) {
            const int w = idx / 3, k = idx % 3;
            float a112 = 0.0f, a20 = 0.0f, a22 = 0.0f;
            #pragma unroll
            for (int u = 0; u < 10; u++) {
                a112 += s_t112[u][k]       * s_W[OW112 + u*10 + w];
                a20  += s_x1[78 + u*3 + k] * s_W[OW20  + u*10 + w];
                a22  += s_t22[u][k]        * s_W[OW22  + u*10 + w];
            }
            oz[78 + idx] = N1E * (a112 + ISQ3 * x20 * a20 + a22);
        }
    } else {
        // warps 4,5 -> r0o (48 outputs over 64 lanes); need d1e[u]
        const int wcopy = wid - 4;
        if (lid < 10) {
            const int u = lid;
            const float b0 = __ldg(&x2z[1]), b1 = __ldg(&x2z[2]), b2 = __ldg(&x2z[3]);
            s_d1e[wcopy][u] = s_x1[78 + u*3 + 0]*b0 + s_x1[78 + u*3 + 1]*b1
                            + s_x1[78 + u*3 + 2]*b2;
        }
        __syncwarp();
        const int w = tid - 128;
        if (w < 48) {
            float acc = 0.0f;
            #pragma unroll
            for (int u = 0; u < 10; u++)
                acc += s_d1e[wcopy][u] * s_W[OW213 + u*48 + w];
            oz[108 + w] = N0O * ISQ3 * acc;
        }
    }
}

extern "C" void kernel_launch(void* const* d_in, const int* in_sizes, int n_in,
                              void* d_out, int out_size)
{
    const float* x1 = (const float*)d_in[0];
    const float* x2 = (const float*)d_in[1];
    const float* W  = (const float*)d_in[2];
    float* out = (float*)d_out;

    const int Z = in_sizes[0] / X1DIM;
    tpthird_kernel<<<Z, 192>>>(x1, x2, W, out);
}